// round 2
// baseline (speedup 1.0000x reference)
#include <cuda_runtime.h>
#include <math.h>

#define Bn 65536
#define Dn 512
#define Rn 64
#define SMS 548            // i-stride (floats) inside big smem tiles: 8*68 + 4 pad, 16B aligned
#define SROW 68            // per-slice stride (floats), conflict-free across s

// ---- device scratch (static globals: no runtime allocation) ----
__device__ float g_Vn[Rn * Dn];            // normalized reflectors, [r][d]
__device__ float g_G[Rn * Rn];             // Gram
__device__ float g_T[Rn * Rn];             // WY T factor (upper triangular)
__device__ float g_Bm[Rn * Dn];            // Bm = T @ Vn, [j][d]
__device__ float g_P[(size_t)Bn * Rn];     // P = X @ Vn^T, 16 MB

// ---- kA: normalize reflector columns ----
__global__ void k_normalize(const float* __restrict__ hp) {
    int r = blockIdx.x;
    int t = threadIdx.x;
    float local = 0.f;
    for (int d = t; d < Dn; d += 128) {
        float v = hp[d * Rn + r];
        local += v * v;
    }
    __shared__ float red[128];
    red[t] = local;
    __syncthreads();
    for (int off = 64; off > 0; off >>= 1) {
        if (t < off) red[t] += red[t + off];
        __syncthreads();
    }
    float inv = 1.0f / sqrtf(red[0]);
    for (int d = t; d < Dn; d += 128) g_Vn[r * Dn + d] = hp[d * Rn + r] * inv;
}

// ---- kB: G = Vn Vn^T ----
__global__ void k_gram() {
    int i = blockIdx.x;
    int t = threadIdx.x;         // 512 threads
    int j = t >> 3, s = t & 7;
    const float* vi = g_Vn + i * Dn + s * 64;
    const float* vj = g_Vn + j * Dn + s * 64;
    float p = 0.f;
#pragma unroll
    for (int q = 0; q < 64; q++) p += vi[q] * vj[q];
    p += __shfl_xor_sync(0xffffffffu, p, 1);
    p += __shfl_xor_sync(0xffffffffu, p, 2);
    p += __shfl_xor_sync(0xffffffffu, p, 4);
    if (s == 0) g_G[i * Rn + j] = p;
}

// ---- kC: T recurrence (single small block, sequential over k) ----
__global__ void k_T() {
    __shared__ float sT[Rn][Rn];
    int j = threadIdx.x;         // 64 threads, thread = row j of T
    for (int k = 0; k < Rn; k++) sT[j][k] = 0.f;
    __syncthreads();
    if (j == 0) sT[0][0] = 2.f;
    __syncthreads();
    for (int k = 1; k < Rn; k++) {
        float s = 0.f;
        if (j < k) {
            for (int m = j; m < k; m++) s += sT[j][m] * g_G[m * Rn + k];
        }
        __syncthreads();
        if (j < k) sT[j][k] = -2.f * s;
        if (j == k) sT[j][k] = 2.f;
        __syncthreads();
    }
    for (int k = 0; k < Rn; k++) g_T[j * Rn + k] = sT[j][k];
}

// ---- kD: Bm = T @ Vn ----
__global__ void k_bm() {
    int j = blockIdx.x;
    int d = threadIdx.x;         // 512 threads = 512 d
    __shared__ float tr[Rn];
    if (d < Rn) tr[d] = g_T[j * Rn + d];
    __syncthreads();
    float acc = 0.f;
    for (int r = j; r < Rn; r++) acc += tr[r] * g_Vn[r * Dn + d];
    g_Bm[j * Dn + d] = acc;
}

// ---- k1: P = X @ Vn^T  (65536 x 64, K=512) ----
// CTA = 64 rows, 512 threads: thread (r = tid/8, s = tid%8) owns k-slice s*64..s*64+63.
// Vn staged in smem layout [i][s][j] (i = k within slice, j contiguous for float4).
__global__ __launch_bounds__(512, 1) void k_xv(const float* __restrict__ X) {
    extern __shared__ float sm[];                 // 64 * SMS floats
    int tid = threadIdx.x;

    // stage Vn -> [i][s][j]
    for (int t = tid; t < Rn * Dn / 4; t += 512) {
        float4 v = ((const float4*)g_Vn)[t];
        int base = t * 4;
        int j = base >> 9;
        int d = base & 511;
        int s = d >> 6, i = d & 63;
        float* p0 = sm + s * SROW + j;
        p0[(i + 0) * SMS] = v.x;
        p0[(i + 1) * SMS] = v.y;
        p0[(i + 2) * SMS] = v.z;
        p0[(i + 3) * SMS] = v.w;
    }
    __syncthreads();

    int r = tid >> 3, s = tid & 7;
    size_t row = (size_t)blockIdx.x * 64 + r;
    const float4* x4p = (const float4*)(X + row * Dn + s * 64);

    float acc[64];
#pragma unroll
    for (int j = 0; j < 64; j++) acc[j] = 0.f;

    const float* vbase = sm + s * SROW;
    for (int i4 = 0; i4 < 16; i4++) {
        float4 x4 = x4p[i4];
#pragma unroll
        for (int u = 0; u < 4; u++) {
            float xi = (u == 0) ? x4.x : (u == 1) ? x4.y : (u == 2) ? x4.z : x4.w;
            const float4* vp = (const float4*)(vbase + (i4 * 4 + u) * SMS);
#pragma unroll
            for (int j4 = 0; j4 < 16; j4++) {
                float4 v = vp[j4];
                acc[j4 * 4 + 0] += xi * v.x;
                acc[j4 * 4 + 1] += xi * v.y;
                acc[j4 * 4 + 2] += xi * v.z;
                acc[j4 * 4 + 3] += xi * v.w;
            }
        }
    }

    // reduce partial dot-products over the 8 k-slices (lanes s = bits 0..2)
#pragma unroll
    for (int j = 0; j < 64; j++) {
        float v = acc[j];
        v += __shfl_xor_sync(0xffffffffu, v, 1);
        v += __shfl_xor_sync(0xffffffffu, v, 2);
        v += __shfl_xor_sync(0xffffffffu, v, 4);
        acc[j] = v;
    }
    if (s == 0) {
        float4* pp = (float4*)(g_P + row * Rn);
#pragma unroll
        for (int j4 = 0; j4 < 16; j4++)
            pp[j4] = make_float4(acc[j4 * 4], acc[j4 * 4 + 1], acc[j4 * 4 + 2], acc[j4 * 4 + 3]);
    }
}

// ---- k2: OUT = X - P @ Bm  (65536 x 512, K=64) ----
// Bm staged in smem layout [j][s][i] (i contiguous for float4 along output d).
__global__ __launch_bounds__(512, 1) void k_out(const float* __restrict__ X,
                                                float* __restrict__ OUT) {
    extern __shared__ float sm[];                 // Bm tile (64*SMS) + P tile (64*SROW)
    float* bms = sm;
    float* sP  = sm + 64 * SMS;
    int tid = threadIdx.x;

    for (int t = tid; t < Rn * Dn / 4; t += 512) {
        float4 v = ((const float4*)g_Bm)[t];
        int base = t * 4;
        int j = base >> 9;
        int d = base & 511;
        int s = d >> 6, i = d & 63;
        *((float4*)(bms + j * SMS + s * SROW + i)) = v;
    }
    size_t rowbase = (size_t)blockIdx.x * 64;
    for (int t = tid; t < 64 * Rn / 4; t += 512) {
        float4 v = ((const float4*)(g_P + rowbase * Rn))[t];
        int rr = t >> 4;
        int c  = (t & 15) * 4;
        *((float4*)(sP + rr * SROW + c)) = v;
    }
    __syncthreads();

    int r = tid >> 3, s = tid & 7;
    size_t row = rowbase + r;
    const float4* x4p = (const float4*)(X + row * Dn + s * 64);

    float4 acc[16];
#pragma unroll
    for (int q = 0; q < 16; q++) acc[q] = x4p[q];

    const float* prow  = sP + r * SROW;
    const float* bbase = bms + s * SROW;
    for (int j = 0; j < 64; j++) {
        float p = prow[j];
        const float4* bp = (const float4*)(bbase + j * SMS);
#pragma unroll
        for (int q = 0; q < 16; q++) {
            float4 b = bp[q];
            acc[q].x -= p * b.x;
            acc[q].y -= p * b.y;
            acc[q].z -= p * b.z;
            acc[q].w -= p * b.w;
        }
    }
    float4* o4p = (float4*)(OUT + row * Dn + s * 64);
#pragma unroll
    for (int q = 0; q < 16; q++) o4p[q] = acc[q];
}

extern "C" void kernel_launch(void* const* d_in, const int* in_sizes, int n_in,
                              void* d_out, int out_size) {
    (void)in_sizes; (void)n_in;
    const float* x    = (const float*)d_in[0];
    const float* sldj = (const float*)d_in[1];
    const float* hp   = (const float*)d_in[2];
    float* out = (float*)d_out;

    const int smem1 = 64 * SMS * 4;                  // 140288 B
    const int smem2 = 64 * SMS * 4 + 64 * SROW * 4;  // 157696 B
    cudaFuncSetAttribute(k_xv,  cudaFuncAttributeMaxDynamicSharedMemorySize, smem1);
    cudaFuncSetAttribute(k_out, cudaFuncAttributeMaxDynamicSharedMemorySize, smem2);

    k_normalize<<<Rn, 128>>>(hp);
    k_gram<<<Rn, 512>>>();
    k_T<<<1, 64>>>();
    k_bm<<<Rn, 512>>>();
    k_xv<<<Bn / 64, 512, smem1>>>(x);
    k_out<<<Bn / 64, 512, smem2>>>(x, out);

    // second output (sldj) is passed through unchanged
    if (out_size >= Bn * Dn + Bn) {
        cudaMemcpyAsync(out + (size_t)Bn * Dn, sldj, Bn * sizeof(float),
                        cudaMemcpyDeviceToDevice);
    }
}

// round 4
// speedup vs baseline: 3.0868x; 3.0868x over previous
#include <cuda_runtime.h>
#include <cuda_bf16.h>
#include <stdint.h>
#include <math.h>

#define Bn 65536
#define Dn 512
#define Rn 64

// ---- device globals (no runtime allocation) ----
__device__ float g_Vn[Rn * Dn];     // normalized reflectors [r][d]
__device__ float g_G[Rn * Rn];
__device__ float g_T[Rn * Rn];
__device__ float g_Bm[Rn * Dn];     // Bm = T @ Vn, [j][d]
__device__ __align__(16) __nv_bfloat16 gVhi[Rn * Dn];   // [r][d]
__device__ __align__(16) __nv_bfloat16 gVlo[Rn * Dn];
__device__ __align__(16) __nv_bfloat16 gB2hi[Dn * Rn];  // [d][j]  (Bm transposed)
__device__ __align__(16) __nv_bfloat16 gB2lo[Dn * Rn];

// bf16 hi/lo split of a float pair -> packed bf16x2 regs (lo element in low half)
__device__ __forceinline__ void split2r(float x, float y, uint32_t& h, uint32_t& l) {
    __nv_bfloat162 hh = __floats2bfloat162_rn(x, y);
    float rx = x - __bfloat162float(hh.x);
    float ry = y - __bfloat162float(hh.y);
    __nv_bfloat162 ll = __floats2bfloat162_rn(rx, ry);
    h = *(uint32_t*)&hh;
    l = *(uint32_t*)&ll;
}

__device__ __forceinline__ void mma16816(float* d, const uint32_t* a, uint32_t b0, uint32_t b1) {
    asm volatile(
        "mma.sync.aligned.m16n8k16.row.col.f32.bf16.bf16.f32 "
        "{%0,%1,%2,%3}, {%4,%5,%6,%7}, {%8,%9}, {%0,%1,%2,%3};"
        : "+f"(d[0]), "+f"(d[1]), "+f"(d[2]), "+f"(d[3])
        : "r"(a[0]), "r"(a[1]), "r"(a[2]), "r"(a[3]), "r"(b0), "r"(b1));
}

// ==================== prep kernels (validated fp32 path) ====================
__global__ void k_normalize(const float* __restrict__ hp) {
    int r = blockIdx.x, t = threadIdx.x;
    float local = 0.f;
    for (int d = t; d < Dn; d += 128) { float v = hp[d * Rn + r]; local += v * v; }
    __shared__ float red[128];
    red[t] = local; __syncthreads();
    for (int off = 64; off > 0; off >>= 1) { if (t < off) red[t] += red[t + off]; __syncthreads(); }
    float inv = 1.0f / sqrtf(red[0]);
    for (int d = t; d < Dn; d += 128) g_Vn[r * Dn + d] = hp[d * Rn + r] * inv;
}

__global__ void k_gram() {
    int i = blockIdx.x, t = threadIdx.x;
    int j = t >> 3, s = t & 7;
    const float* vi = g_Vn + i * Dn + s * 64;
    const float* vj = g_Vn + j * Dn + s * 64;
    float p = 0.f;
#pragma unroll
    for (int q = 0; q < 64; q++) p += vi[q] * vj[q];
    p += __shfl_xor_sync(0xffffffffu, p, 1);
    p += __shfl_xor_sync(0xffffffffu, p, 2);
    p += __shfl_xor_sync(0xffffffffu, p, 4);
    if (s == 0) g_G[i * Rn + j] = p;
}

__global__ void k_T() {
    __shared__ float sT[Rn][Rn];
    int j = threadIdx.x;
    for (int k = 0; k < Rn; k++) sT[j][k] = 0.f;
    __syncthreads();
    if (j == 0) sT[0][0] = 2.f;
    __syncthreads();
    for (int k = 1; k < Rn; k++) {
        float s = 0.f;
        if (j < k) for (int m = j; m < k; m++) s += sT[j][m] * g_G[m * Rn + k];
        __syncthreads();
        if (j < k) sT[j][k] = -2.f * s;
        if (j == k) sT[j][k] = 2.f;
        __syncthreads();
    }
    for (int k = 0; k < Rn; k++) g_T[j * Rn + k] = sT[j][k];
}

__global__ void k_bm() {
    int j = blockIdx.x, d = threadIdx.x;
    __shared__ float tr[Rn];
    if (d < Rn) tr[d] = g_T[j * Rn + d];
    __syncthreads();
    float acc = 0.f;
#pragma unroll
    for (int r = 0; r < Rn; r++) acc += tr[r] * g_Vn[r * Dn + d];   // T[j][r]=0 for r<j
    g_Bm[j * Dn + d] = acc;
}

__global__ void k_split() {
    int b = blockIdx.x, t = threadIdx.x;
    if (b < Rn) {
        float v = g_Vn[b * Dn + t];
        __nv_bfloat16 h = __float2bfloat16(v);
        gVhi[b * Dn + t] = h;
        gVlo[b * Dn + t] = __float2bfloat16(v - __bfloat162float(h));
    } else {
        int j = b - Rn;
        float v = g_Bm[j * Dn + t];
        __nv_bfloat16 h = __float2bfloat16(v);
        gB2hi[t * Rn + j] = h;
        gB2lo[t * Rn + j] = __float2bfloat16(v - __bfloat162float(h));
    }
}

// ==================== main fused HMMA kernel ====================
// CTA = 128 rows, 8 warps x 16 rows. GEMM1: P = X V^T (K=512, 4 k-chunks of 128).
// P stays in registers (negated bf16 hi/lo). GEMM2: OUT = X + (-P) Bm, 8 n-chunks of 64.
// smem: hi tile @0 (17408 B), lo tile @17408 — V chunk [64][136] bf16, later BmT [64][72].
__global__ __launch_bounds__(256, 2) void k_main(const float* __restrict__ X,
                                                 float* __restrict__ OUT) {
    extern __shared__ char smem[];
    __nv_bfloat16* sHi = (__nv_bfloat16*)smem;
    __nv_bfloat16* sLo = (__nv_bfloat16*)(smem + 17408);
    const uint32_t* sHi32 = (const uint32_t*)sHi;
    const uint32_t* sLo32 = (const uint32_t*)sLo;

    const int tid = threadIdx.x;
    const int wid = tid >> 5;
    const int lane = tid & 31;
    const int qid = lane >> 2;     // 0..7
    const int qtr = lane & 3;      // 0..3

    const int r0 = blockIdx.x * 128 + wid * 16 + qid;
    const float* xrow0 = X + (size_t)r0 * Dn;
    const float* xrow1 = xrow0 + 8 * Dn;

    // -------- GEMM1: P[16x64 per warp] = X * V^T --------
    float acc[8][4];
#pragma unroll
    for (int f = 0; f < 8; f++)
#pragma unroll
        for (int q = 0; q < 4; q++) acc[f][q] = 0.f;

    for (int kc = 0; kc < 4; kc++) {
        __syncthreads();
        // stage V chunk [64 n][128 k] bf16 hi/lo, padded stride 136
        for (int it = tid; it < 1024; it += 256) {
            int n = it >> 4, seg = it & 15;
            *(uint4*)(sHi + n * 136 + seg * 8) =
                *(const uint4*)(gVhi + n * Dn + kc * 128 + seg * 8);
            *(uint4*)(sLo + n * 136 + seg * 8) =
                *(const uint4*)(gVlo + n * Dn + kc * 128 + seg * 8);
        }
        __syncthreads();
#pragma unroll
        for (int kk = 0; kk < 8; kk++) {
            int c0 = kc * 128 + kk * 16 + qtr * 2;
            float2 x00 = *(const float2*)(xrow0 + c0);
            float2 x10 = *(const float2*)(xrow1 + c0);
            float2 x01 = *(const float2*)(xrow0 + c0 + 8);
            float2 x11 = *(const float2*)(xrow1 + c0 + 8);
            uint32_t ah[4], al[4];
            split2r(x00.x, x00.y, ah[0], al[0]);
            split2r(x10.x, x10.y, ah[1], al[1]);
            split2r(x01.x, x01.y, ah[2], al[2]);
            split2r(x11.x, x11.y, ah[3], al[3]);
            int kidx = kk * 8 + qtr;
#pragma unroll
            for (int nt = 0; nt < 8; nt++) {
                int n = nt * 8 + qid;
                uint32_t bh0 = sHi32[n * 68 + kidx];
                uint32_t bh1 = sHi32[n * 68 + kidx + 4];
                uint32_t bl0 = sLo32[n * 68 + kidx];
                uint32_t bl1 = sLo32[n * 68 + kidx + 4];
                mma16816(acc[nt], ah, bh0, bh1);
                mma16816(acc[nt], ah, bl0, bl1);
                mma16816(acc[nt], al, bh0, bh1);
            }
        }
    }

    // -------- P -> negated bf16 hi/lo in registers (A frags of GEMM2) --------
    uint32_t Ph[16], Pl[16];
#pragma unroll
    for (int f = 0; f < 8; f++) {
        split2r(-acc[f][0], -acc[f][1], Ph[2 * f],     Pl[2 * f]);
        split2r(-acc[f][2], -acc[f][3], Ph[2 * f + 1], Pl[2 * f + 1]);
    }

    // -------- GEMM2: OUT = X + (-P) * Bm, 8 chunks of 64 output cols --------
    float* orow0 = OUT + (size_t)r0 * Dn;
    float* orow1 = orow0 + 8 * Dn;
    for (int nc = 0; nc < 8; nc++) {
        __syncthreads();
        // stage BmT chunk [64 d][64 j] bf16 hi/lo, padded stride 72
        for (int it = tid; it < 512; it += 256) {
            int dl = it >> 3, seg = it & 7;
            *(uint4*)(sHi + dl * 72 + seg * 8) =
                *(const uint4*)(gB2hi + (size_t)(nc * 64 + dl) * Rn + seg * 8);
            *(uint4*)(sLo + dl * 72 + seg * 8) =
                *(const uint4*)(gB2lo + (size_t)(nc * 64 + dl) * Rn + seg * 8);
        }
        __syncthreads();

        float acc2[8][4];
        int cb = nc * 64 + qtr * 2;
#pragma unroll
        for (int nt = 0; nt < 8; nt++) {
            float2 t0 = *(const float2*)(xrow0 + cb + nt * 8);
            float2 t1 = *(const float2*)(xrow1 + cb + nt * 8);
            acc2[nt][0] = t0.x; acc2[nt][1] = t0.y;
            acc2[nt][2] = t1.x; acc2[nt][3] = t1.y;
        }
#pragma unroll
        for (int kk = 0; kk < 4; kk++) {
            int kidx = kk * 8 + qtr;
#pragma unroll
            for (int nt = 0; nt < 8; nt++) {
                int dl = nt * 8 + qid;
                uint32_t bh0 = sHi32[dl * 36 + kidx];
                uint32_t bh1 = sHi32[dl * 36 + kidx + 4];
                uint32_t bl0 = sLo32[dl * 36 + kidx];
                uint32_t bl1 = sLo32[dl * 36 + kidx + 4];
                mma16816(acc2[nt], Ph + 4 * kk, bh0, bh1);
                mma16816(acc2[nt], Ph + 4 * kk, bl0, bl1);
                mma16816(acc2[nt], Pl + 4 * kk, bh0, bh1);
            }
        }
#pragma unroll
        for (int nt = 0; nt < 8; nt++) {
            *(float2*)(orow0 + cb + nt * 8) = make_float2(acc2[nt][0], acc2[nt][1]);
            *(float2*)(orow1 + cb + nt * 8) = make_float2(acc2[nt][2], acc2[nt][3]);
        }
    }
}

extern "C" void kernel_launch(void* const* d_in, const int* in_sizes, int n_in,
                              void* d_out, int out_size) {
    (void)in_sizes; (void)n_in;
    const float* x    = (const float*)d_in[0];
    const float* sldj = (const float*)d_in[1];
    const float* hp   = (const float*)d_in[2];
    float* out = (float*)d_out;

    const int smem_main = 2 * 64 * 136 * 2;   // 34816 B
    cudaFuncSetAttribute(k_main, cudaFuncAttributeMaxDynamicSharedMemorySize, smem_main);

    k_normalize<<<Rn, 128>>>(hp);
    k_gram<<<Rn, 512>>>();
    k_T<<<1, 64>>>();
    k_bm<<<Rn, 512>>>();
    k_split<<<128, 512>>>();
    k_main<<<Bn / 128, 256, smem_main>>>(x, out);

    if (out_size >= Bn * Dn + Bn) {
        cudaMemcpyAsync(out + (size_t)Bn * Dn, sldj, Bn * sizeof(float),
                        cudaMemcpyDeviceToDevice);
    }
}

// round 6
// speedup vs baseline: 3.3787x; 1.0946x over previous
#include <cuda_runtime.h>
#include <cuda_bf16.h>
#include <stdint.h>
#include <math.h>

#define Bn 65536
#define Dn 512
#define Rn 64

// smem (bytes): GEMM1: Vhi [64][520]b16 @0 (66560), Vlo @66560. total 133120
//               GEMM2: BmT hi [512][72]b16 @0 (73728), lo @73728. total 147456
#define SMEM_MAIN 147456

__device__ float g_Vn[Rn * Dn];     // normalized reflectors [r][d]
__device__ float g_G[Rn * Rn];
__device__ float g_T[Rn * Rn];
__device__ __align__(16) __nv_bfloat16 gVhi[Rn * Dn];   // [r][d]
__device__ __align__(16) __nv_bfloat16 gVlo[Rn * Dn];
__device__ __align__(16) __nv_bfloat16 gB2hi[Dn * Rn];  // [d][j]  (Bm transposed)
__device__ __align__(16) __nv_bfloat16 gB2lo[Dn * Rn];

__device__ __forceinline__ uint32_t s2u(const void* p) {
    uint32_t a;
    asm("{ .reg .u64 t; cvta.to.shared.u64 t, %1; cvt.u32.u64 %0, t; }" : "=r"(a) : "l"(p));
    return a;
}

__device__ __forceinline__ void split2r(float x, float y, uint32_t& h, uint32_t& l) {
    __nv_bfloat162 hh = __floats2bfloat162_rn(x, y);
    float rx = x - __bfloat162float(hh.x);
    float ry = y - __bfloat162float(hh.y);
    __nv_bfloat162 ll = __floats2bfloat162_rn(rx, ry);
    h = *(uint32_t*)&hh;
    l = *(uint32_t*)&ll;
}

__device__ __forceinline__ void mma16816(float* d, const uint32_t* a, uint32_t b0, uint32_t b1) {
    asm volatile(
        "mma.sync.aligned.m16n8k16.row.col.f32.bf16.bf16.f32 "
        "{%0,%1,%2,%3}, {%4,%5,%6,%7}, {%8,%9}, {%0,%1,%2,%3};"
        : "+f"(d[0]), "+f"(d[1]), "+f"(d[2]), "+f"(d[3])
        : "r"(a[0]), "r"(a[1]), "r"(a[2]), "r"(a[3]), "r"(b0), "r"(b1));
}

__device__ __forceinline__ void ldsm4(uint32_t addr, uint32_t* r) {
    asm volatile("ldmatrix.sync.aligned.m8n8.x4.shared.b16 {%0,%1,%2,%3}, [%4];"
                 : "=r"(r[0]), "=r"(r[1]), "=r"(r[2]), "=r"(r[3]) : "r"(addr));
}

// ==================== prep kernels ====================
__global__ void k_normalize(const float* __restrict__ hp) {
    int r = blockIdx.x, t = threadIdx.x;
    float local = 0.f;
    for (int d = t; d < Dn; d += 128) { float v = hp[d * Rn + r]; local += v * v; }
    __shared__ float red[128];
    red[t] = local; __syncthreads();
    for (int off = 64; off > 0; off >>= 1) { if (t < off) red[t] += red[t + off]; __syncthreads(); }
    float inv = 1.0f / sqrtf(red[0]);
    for (int d = t; d < Dn; d += 128) {
        float v = hp[d * Rn + r] * inv;
        g_Vn[r * Dn + d] = v;
        __nv_bfloat16 h = __float2bfloat16(v);
        gVhi[r * Dn + d] = h;
        gVlo[r * Dn + d] = __float2bfloat16(v - __bfloat162float(h));
    }
}

__global__ void k_gram() {
    int i = blockIdx.x, t = threadIdx.x;
    int j = t >> 3, s = t & 7;
    const float* vi = g_Vn + i * Dn + s * 64;
    const float* vj = g_Vn + j * Dn + s * 64;
    float p = 0.f;
#pragma unroll
    for (int q = 0; q < 64; q++) p += vi[q] * vj[q];
    p += __shfl_xor_sync(0xffffffffu, p, 1);
    p += __shfl_xor_sync(0xffffffffu, p, 2);
    p += __shfl_xor_sync(0xffffffffu, p, 4);
    if (s == 0) g_G[i * Rn + j] = p;
}

__global__ void k_T() {
    __shared__ float sT[Rn][Rn];
    int j = threadIdx.x;
    for (int k = 0; k < Rn; k++) sT[j][k] = 0.f;
    __syncthreads();
    if (j == 0) sT[0][0] = 2.f;
    __syncthreads();
    for (int k = 1; k < Rn; k++) {
        float s = 0.f;
        if (j < k) for (int m = j; m < k; m++) s += sT[j][m] * g_G[m * Rn + k];
        __syncthreads();
        if (j < k) sT[j][k] = -2.f * s;
        if (j == k) sT[j][k] = 2.f;
        __syncthreads();
    }
    for (int k = 0; k < Rn; k++) g_T[j * Rn + k] = sT[j][k];
}

// Bm = T @ Vn, fused with the bf16 hi/lo split + transpose store
__global__ void k_bmsplit() {
    int j = blockIdx.x, d = threadIdx.x;
    __shared__ float tr[Rn];
    if (d < Rn) tr[d] = g_T[j * Rn + d];
    __syncthreads();
    float acc = 0.f;
#pragma unroll
    for (int r = 0; r < Rn; r++) acc += tr[r] * g_Vn[r * Dn + d];
    __nv_bfloat16 h = __float2bfloat16(acc);
    gB2hi[d * Rn + j] = h;
    gB2lo[d * Rn + j] = __float2bfloat16(acc - __bfloat162float(h));
}

// ==================== main fused HMMA kernel ====================
// CTA = 256 rows, 16 warps x 16 rows. All of V (hi/lo) resident in smem for
// GEMM1 (K=512, no barriers); then all of BmT resident for GEMM2 (8 n-chunks).
// B fragments via ldmatrix.x4; P lives in registers (negated bf16 hi/lo).
__global__ __launch_bounds__(512, 1) void k_main(const float* __restrict__ X,
                                                 float* __restrict__ OUT) {
    extern __shared__ char smem[];
    const uint32_t sHi = s2u(smem);

    const int tid = threadIdx.x;
    const int wid = tid >> 5;
    const int lane = tid & 31;
    const int qid = lane >> 2;     // 0..7
    const int qtr = lane & 3;      // 0..3

    // per-lane ldmatrix row id: matrices m0,m1 -> n-rows 0..7 ; m2,m3 -> +8
    const int base_n = ((lane >> 4) & 1) * 8 + (lane & 7);
    const int koff   = ((lane >> 3) & 1) * 8;     // m1,m3 -> k half +8

    const int r0 = blockIdx.x * 256 + wid * 16 + qid;
    const float* xrow0 = X + (size_t)r0 * Dn;
    const float* xrow1 = xrow0 + 8 * Dn;

    // ---- stage ALL of V hi/lo: [64 n][520 pad] bf16 ----
    {
        __nv_bfloat16* dsthi = (__nv_bfloat16*)smem;
        __nv_bfloat16* dstlo = (__nv_bfloat16*)(smem + 66560);
        for (int i = tid; i < 4096; i += 512) {
            int n = i >> 6, seg = i & 63;
            *(uint4*)(dsthi + n * 520 + seg * 8) = *(const uint4*)(gVhi + n * Dn + seg * 8);
            *(uint4*)(dstlo + n * 520 + seg * 8) = *(const uint4*)(gVlo + n * Dn + seg * 8);
        }
    }
    __syncthreads();

    // ---- GEMM1: P[16x64 per warp] = X * V^T, K=512, zero barriers ----
    float acc[8][4];
#pragma unroll
    for (int f = 0; f < 8; f++)
#pragma unroll
        for (int q = 0; q < 4; q++) acc[f][q] = 0.f;

    const uint32_t aV = sHi + (uint32_t)(base_n * 520 + koff) * 2;

#pragma unroll 2
    for (int kk = 0; kk < 32; kk++) {
        int c0 = kk * 16 + qtr * 2;
        float2 x00 = *(const float2*)(xrow0 + c0);
        float2 x10 = *(const float2*)(xrow1 + c0);
        float2 x01 = *(const float2*)(xrow0 + c0 + 8);
        float2 x11 = *(const float2*)(xrow1 + c0 + 8);
        uint32_t ah[4], al[4];
        split2r(x00.x, x00.y, ah[0], al[0]);
        split2r(x10.x, x10.y, ah[1], al[1]);
        split2r(x01.x, x01.y, ah[2], al[2]);
        split2r(x11.x, x11.y, ah[3], al[3]);
        uint32_t ak = aV + (uint32_t)kk * 32;
#pragma unroll
        for (int ntp = 0; ntp < 4; ntp++) {
            uint32_t bh[4], bl[4];
            ldsm4(ak + ntp * 16640u, bh);            // n-block 2ntp (m0,m1) & 2ntp+1 (m2,m3)
            ldsm4(ak + ntp * 16640u + 66560u, bl);
            mma16816(acc[2 * ntp],     ah, bh[0], bh[1]);
            mma16816(acc[2 * ntp],     ah, bl[0], bl[1]);
            mma16816(acc[2 * ntp],     al, bh[0], bh[1]);
            mma16816(acc[2 * ntp + 1], ah, bh[2], bh[3]);
            mma16816(acc[2 * ntp + 1], ah, bl[2], bl[3]);
            mma16816(acc[2 * ntp + 1], al, bh[2], bh[3]);
        }
    }

    // ---- P -> negated bf16 hi/lo register fragments (A of GEMM2) ----
    uint32_t Ph[16], Pl[16];
#pragma unroll
    for (int f = 0; f < 8; f++) {
        split2r(-acc[f][0], -acc[f][1], Ph[2 * f],     Pl[2 * f]);
        split2r(-acc[f][2], -acc[f][3], Ph[2 * f + 1], Pl[2 * f + 1]);
    }

    // ---- restage smem: BmT hi/lo [512 d][72 pad] bf16 ----
    __syncthreads();
    {
        __nv_bfloat16* dsthi = (__nv_bfloat16*)smem;
        __nv_bfloat16* dstlo = (__nv_bfloat16*)(smem + 73728);
        for (int i = tid; i < 4096; i += 512) {
            int d = i >> 3, seg = i & 7;
            *(uint4*)(dsthi + d * 72 + seg * 8) = *(const uint4*)(gB2hi + d * Rn + seg * 8);
            *(uint4*)(dstlo + d * 72 + seg * 8) = *(const uint4*)(gB2lo + d * Rn + seg * 8);
        }
    }
    __syncthreads();

    // ---- GEMM2: OUT = X + (-P) * Bm, 8 chunks of 64 cols, zero barriers ----
    float* orow0 = OUT + (size_t)r0 * Dn;
    float* orow1 = orow0 + 8 * Dn;
    const uint32_t aB = sHi + (uint32_t)(base_n * 72 + koff) * 2;

    for (int nc = 0; nc < 8; nc++) {
        float acc2[8][4];
        int cb = nc * 64 + qtr * 2;
#pragma unroll
        for (int nt = 0; nt < 8; nt++) {
            float2 t0 = *(const float2*)(xrow0 + cb + nt * 8);
            float2 t1 = *(const float2*)(xrow1 + cb + nt * 8);
            acc2[nt][0] = t0.x; acc2[nt][1] = t0.y;
            acc2[nt][2] = t1.x; acc2[nt][3] = t1.y;
        }
        uint32_t an = aB + (uint32_t)nc * 9216;
#pragma unroll
        for (int kk = 0; kk < 4; kk++) {
            uint32_t ak = an + (uint32_t)kk * 32;
#pragma unroll
            for (int ntp = 0; ntp < 4; ntp++) {
                uint32_t bh[4], bl[4];
                ldsm4(ak + ntp * 2304u, bh);
                ldsm4(ak + ntp * 2304u + 73728u, bl);
                mma16816(acc2[2 * ntp],     Ph + 4 * kk, bh[0], bh[1]);
                mma16816(acc2[2 * ntp],     Ph + 4 * kk, bl[0], bl[1]);
                mma16816(acc2[2 * ntp],     Pl + 4 * kk, bh[0], bh[1]);
                mma16816(acc2[2 * ntp + 1], Ph + 4 * kk, bh[2], bh[3]);
                mma16816(acc2[2 * ntp + 1], Ph + 4 * kk, bl[2], bl[3]);
                mma16816(acc2[2 * ntp + 1], Pl + 4 * kk, bh[2], bh[3]);
            }
        }
#pragma unroll
        for (int nt = 0; nt < 8; nt++) {
            *(float2*)(orow0 + cb + nt * 8) = make_float2(acc2[nt][0], acc2[nt][1]);
            *(float2*)(orow1 + cb + nt * 8) = make_float2(acc2[nt][2], acc2[nt][3]);
        }
    }
}

extern "C" void kernel_launch(void* const* d_in, const int* in_sizes, int n_in,
                              void* d_out, int out_size) {
    (void)in_sizes; (void)n_in;
    const float* x    = (const float*)d_in[0];
    const float* sldj = (const float*)d_in[1];
    const float* hp   = (const float*)d_in[2];
    float* out = (float*)d_out;

    cudaFuncSetAttribute(k_main, cudaFuncAttributeMaxDynamicSharedMemorySize, SMEM_MAIN);

    k_normalize<<<Rn, 128>>>(hp);
    k_gram<<<Rn, 512>>>();
    k_T<<<1, 64>>>();
    k_bmsplit<<<Rn, 512>>>();
    k_main<<<Bn / 256, 512, SMEM_MAIN>>>(x, out);

    if (out_size >= Bn * Dn + Bn) {
        cudaMemcpyAsync(out + (size_t)Bn * Dn, sldj, Bn * sizeof(float),
                        cudaMemcpyDeviceToDevice);
    }
}

// round 7
// speedup vs baseline: 3.4166x; 1.0112x over previous
#include <cuda_runtime.h>
#include <cuda_fp16.h>
#include <stdint.h>
#include <math.h>

#define Bn 65536
#define Dn 512
#define Rn 64

// smem (bytes): GEMM1: Vhi [64][520]f16 @0 (66560), Vlo @66560. total 133120
//               GEMM2: BmT hi [512][72]f16 @0 (73728), lo @73728. total 147456
#define SMEM_MAIN 147456

__device__ float g_Vn[Rn * Dn];     // normalized reflectors [r][d]
__device__ float g_G[Rn * Rn];
__device__ float g_T[Rn * Rn];
__device__ __align__(16) __half gVhi[Rn * Dn];   // fp16(v), [r][d]
__device__ __align__(16) __half gVlo[Rn * Dn];   // fp16(v - fp16(v))
__device__ __align__(16) __half gB2hi[Dn * Rn];  // [d][j]  (Bm transposed)
__device__ __align__(16) __half gB2lo[Dn * Rn];

__device__ __forceinline__ uint32_t s2u(const void* p) {
    uint32_t a;
    asm("{ .reg .u64 t; cvta.to.shared.u64 t, %1; cvt.u32.u64 %0, t; }" : "=r"(a) : "l"(p));
    return a;
}

__device__ __forceinline__ uint32_t pack_h2(float x, float y) {
    __half2 h = __floats2half2_rn(x, y);
    return *(uint32_t*)&h;
}

__device__ __forceinline__ void mma16816(float* d, const uint32_t* a, uint32_t b0, uint32_t b1) {
    asm volatile(
        "mma.sync.aligned.m16n8k16.row.col.f32.f16.f16.f32 "
        "{%0,%1,%2,%3}, {%4,%5,%6,%7}, {%8,%9}, {%0,%1,%2,%3};"
        : "+f"(d[0]), "+f"(d[1]), "+f"(d[2]), "+f"(d[3])
        : "r"(a[0]), "r"(a[1]), "r"(a[2]), "r"(a[3]), "r"(b0), "r"(b1));
}

__device__ __forceinline__ void ldsm4(uint32_t addr, uint32_t* r) {
    asm volatile("ldmatrix.sync.aligned.m8n8.x4.shared.b16 {%0,%1,%2,%3}, [%4];"
                 : "=r"(r[0]), "=r"(r[1]), "=r"(r[2]), "=r"(r[3]) : "r"(addr));
}

// ==================== prep kernels ====================
__global__ void k_normalize(const float* __restrict__ hp) {
    int r = blockIdx.x, t = threadIdx.x;
    float local = 0.f;
    for (int d = t; d < Dn; d += 128) { float v = hp[d * Rn + r]; local += v * v; }
    __shared__ float red[128];
    red[t] = local; __syncthreads();
    for (int off = 64; off > 0; off >>= 1) { if (t < off) red[t] += red[t + off]; __syncthreads(); }
    float inv = 1.0f / sqrtf(red[0]);
    for (int d = t; d < Dn; d += 128) {
        float v = hp[d * Rn + r] * inv;
        g_Vn[r * Dn + d] = v;
        __half h = __float2half_rn(v);
        gVhi[r * Dn + d] = h;
        gVlo[r * Dn + d] = __float2half_rn(v - __half2float(h));
    }
}

__global__ void k_gram() {
    int i = blockIdx.x, t = threadIdx.x;
    int j = t >> 3, s = t & 7;
    const float* vi = g_Vn + i * Dn + s * 64;
    const float* vj = g_Vn + j * Dn + s * 64;
    float p = 0.f;
#pragma unroll
    for (int q = 0; q < 64; q++) p += vi[q] * vj[q];
    p += __shfl_xor_sync(0xffffffffu, p, 1);
    p += __shfl_xor_sync(0xffffffffu, p, 2);
    p += __shfl_xor_sync(0xffffffffu, p, 4);
    if (s == 0) g_G[i * Rn + j] = p;
}

__global__ void k_T() {
    __shared__ float sT[Rn][Rn];
    int j = threadIdx.x;
    for (int k = 0; k < Rn; k++) sT[j][k] = 0.f;
    __syncthreads();
    if (j == 0) sT[0][0] = 2.f;
    __syncthreads();
    for (int k = 1; k < Rn; k++) {
        float s = 0.f;
        if (j < k) for (int m = j; m < k; m++) s += sT[j][m] * g_G[m * Rn + k];
        __syncthreads();
        if (j < k) sT[j][k] = -2.f * s;
        if (j == k) sT[j][k] = 2.f;
        __syncthreads();
    }
    for (int k = 0; k < Rn; k++) g_T[j * Rn + k] = sT[j][k];
}

// Bm = T @ Vn, fused with the fp16 hi/lo split + transpose store
__global__ void k_bmsplit() {
    int j = blockIdx.x, d = threadIdx.x;
    __shared__ float tr[Rn];
    if (d < Rn) tr[d] = g_T[j * Rn + d];
    __syncthreads();
    float acc = 0.f;
#pragma unroll
    for (int r = 0; r < Rn; r++) acc += tr[r] * g_Vn[r * Dn + d];
    __half h = __float2half_rn(acc);
    gB2hi[d * Rn + j] = h;
    gB2lo[d * Rn + j] = __float2half_rn(acc - __half2float(h));
}

// ==================== main fused HMMA kernel (fp16 2-term) ====================
// CTA = 256 rows, 16 warps x 16 rows. All of V (hi/lo) resident in smem for
// GEMM1 (K=512, no barriers); then all of BmT resident for GEMM2 (8 n-chunks).
// A operands (X, P) as single fp16; B operands carry the fp16 hi/lo split.
__global__ __launch_bounds__(512, 1) void k_main(const float* __restrict__ X,
                                                 float* __restrict__ OUT) {
    extern __shared__ char smem[];
    const uint32_t sHi = s2u(smem);

    const int tid = threadIdx.x;
    const int wid = tid >> 5;
    const int lane = tid & 31;
    const int qid = lane >> 2;     // 0..7
    const int qtr = lane & 3;      // 0..3

    const int base_n = ((lane >> 4) & 1) * 8 + (lane & 7);
    const int koff   = ((lane >> 3) & 1) * 8;

    const int r0 = blockIdx.x * 256 + wid * 16 + qid;
    const float* xrow0 = X + (size_t)r0 * Dn;
    const float* xrow1 = xrow0 + 8 * Dn;

    // ---- stage ALL of V hi/lo: [64 n][520 pad] f16 ----
    {
        __half* dsthi = (__half*)smem;
        __half* dstlo = (__half*)(smem + 66560);
        for (int i = tid; i < 4096; i += 512) {
            int n = i >> 6, seg = i & 63;
            *(uint4*)(dsthi + n * 520 + seg * 8) = *(const uint4*)(gVhi + n * Dn + seg * 8);
            *(uint4*)(dstlo + n * 520 + seg * 8) = *(const uint4*)(gVlo + n * Dn + seg * 8);
        }
    }
    __syncthreads();

    // ---- GEMM1: P[16x64 per warp] = X * V^T, K=512, zero barriers ----
    float acc[8][4];
#pragma unroll
    for (int f = 0; f < 8; f++)
#pragma unroll
        for (int q = 0; q < 4; q++) acc[f][q] = 0.f;

    const uint32_t aV = sHi + (uint32_t)(base_n * 520 + koff) * 2;

#pragma unroll 2
    for (int kk = 0; kk < 32; kk++) {
        int c0 = kk * 16 + qtr * 2;
        float2 x00 = *(const float2*)(xrow0 + c0);
        float2 x10 = *(const float2*)(xrow1 + c0);
        float2 x01 = *(const float2*)(xrow0 + c0 + 8);
        float2 x11 = *(const float2*)(xrow1 + c0 + 8);
        uint32_t a[4];
        a[0] = pack_h2(x00.x, x00.y);
        a[1] = pack_h2(x10.x, x10.y);
        a[2] = pack_h2(x01.x, x01.y);
        a[3] = pack_h2(x11.x, x11.y);
        uint32_t ak = aV + (uint32_t)kk * 32;
#pragma unroll
        for (int ntp = 0; ntp < 4; ntp++) {
            uint32_t bh[4], bl[4];
            ldsm4(ak + ntp * 16640u, bh);
            ldsm4(ak + ntp * 16640u + 66560u, bl);
            mma16816(acc[2 * ntp],     a, bh[0], bh[1]);
            mma16816(acc[2 * ntp],     a, bl[0], bl[1]);
            mma16816(acc[2 * ntp + 1], a, bh[2], bh[3]);
            mma16816(acc[2 * ntp + 1], a, bl[2], bl[3]);
        }
    }

    // ---- P -> negated fp16 register fragments (A of GEMM2) ----
    uint32_t Pq[16];
#pragma unroll
    for (int f = 0; f < 8; f++) {
        Pq[2 * f]     = pack_h2(-acc[f][0], -acc[f][1]);
        Pq[2 * f + 1] = pack_h2(-acc[f][2], -acc[f][3]);
    }

    // ---- restage smem: BmT hi/lo [512 d][72 pad] f16 ----
    __syncthreads();
    {
        __half* dsthi = (__half*)smem;
        __half* dstlo = (__half*)(smem + 73728);
        for (int i = tid; i < 4096; i += 512) {
            int d = i >> 3, seg = i & 7;
            *(uint4*)(dsthi + d * 72 + seg * 8) = *(const uint4*)(gB2hi + d * Rn + seg * 8);
            *(uint4*)(dstlo + d * 72 + seg * 8) = *(const uint4*)(gB2lo + d * Rn + seg * 8);
        }
    }
    __syncthreads();

    // ---- GEMM2: OUT = X + (-P) * Bm, 8 chunks of 64 cols, zero barriers ----
    float* orow0 = OUT + (size_t)r0 * Dn;
    float* orow1 = orow0 + 8 * Dn;
    const uint32_t aB = sHi + (uint32_t)(base_n * 72 + koff) * 2;

    for (int nc = 0; nc < 8; nc++) {
        float acc2[8][4];
        int cb = nc * 64 + qtr * 2;
#pragma unroll
        for (int nt = 0; nt < 8; nt++) {
            float2 t0 = *(const float2*)(xrow0 + cb + nt * 8);
            float2 t1 = *(const float2*)(xrow1 + cb + nt * 8);
            acc2[nt][0] = t0.x; acc2[nt][1] = t0.y;
            acc2[nt][2] = t1.x; acc2[nt][3] = t1.y;
        }
        uint32_t an = aB + (uint32_t)nc * 9216;
#pragma unroll
        for (int kk = 0; kk < 4; kk++) {
            uint32_t ak = an + (uint32_t)kk * 32;
#pragma unroll
            for (int ntp = 0; ntp < 4; ntp++) {
                uint32_t bh[4], bl[4];
                ldsm4(ak + ntp * 2304u, bh);
                ldsm4(ak + ntp * 2304u + 73728u, bl);
                mma16816(acc2[2 * ntp],     Pq + 4 * kk, bh[0], bh[1]);
                mma16816(acc2[2 * ntp],     Pq + 4 * kk, bl[0], bl[1]);
                mma16816(acc2[2 * ntp + 1], Pq + 4 * kk, bh[2], bh[3]);
                mma16816(acc2[2 * ntp + 1], Pq + 4 * kk, bl[2], bl[3]);
            }
        }
#pragma unroll
        for (int nt = 0; nt < 8; nt++) {
            *(float2*)(orow0 + cb + nt * 8) = make_float2(acc2[nt][0], acc2[nt][1]);
            *(float2*)(orow1 + cb + nt * 8) = make_float2(acc2[nt][2], acc2[nt][3]);
        }
    }
}

extern "C" void kernel_launch(void* const* d_in, const int* in_sizes, int n_in,
                              void* d_out, int out_size) {
    (void)in_sizes; (void)n_in;
    const float* x    = (const float*)d_in[0];
    const float* sldj = (const float*)d_in[1];
    const float* hp   = (const float*)d_in[2];
    float* out = (float*)d_out;

    cudaFuncSetAttribute(k_main, cudaFuncAttributeMaxDynamicSharedMemorySize, SMEM_MAIN);

    k_normalize<<<Rn, 128>>>(hp);
    k_gram<<<Rn, 512>>>();
    k_T<<<1, 64>>>();
    k_bmsplit<<<Rn, 512>>>();
    k_main<<<Bn / 256, 512, SMEM_MAIN>>>(x, out);

    if (out_size >= Bn * Dn + Bn) {
        cudaMemcpyAsync(out + (size_t)Bn * Dn, sldj, Bn * sizeof(float),
                        cudaMemcpyDeviceToDevice);
    }
}